// round 12
// baseline (speedup 1.0000x reference)
#include <cuda_runtime.h>
#include <cuda_bf16.h>
#include <cuda_fp16.h>
#include <cstdint>
#include <climits>

#define BATCH 8192
#define DIN   768
#define DH    16384
#define TK    32
#define CMAX  448
#define NBIN  8192          // bf16-bits >> 2
#define CUMTGT 48

// ---- scratch (static device globals; no dynamic allocation) ----
__device__ __nv_bfloat16 g_zb[(size_t)BATCH * DH];   // 256 MB post-relu activations (bf16)
__device__ __half g_wdth[(size_t)DH * DIN];          // 24 MB transposed W_dec (fp16)
__device__ int8_t g_x8[(size_t)BATCH * DIN];         // int8 x (per-row scale)
__device__ int8_t g_w8[(size_t)DH * DIN];            // int8 W_enc (per-row scale)
__device__ float  g_sx[BATCH];
__device__ float  g_sw[DH];
__device__ int    g_candi[(size_t)BATCH * CMAX];
__device__ int    g_candcnt[BATCH];

// ======================================================================
// helpers (all target-independent PTX: cp.async, ldmatrix, mma.sync)
// ======================================================================
__device__ __forceinline__ uint32_t smem_u32(const void* p) {
    uint32_t a;
    asm("{ .reg .u64 t; cvta.to.shared.u64 t, %1; cvt.u32.u64 %0, t; }" : "=r"(a) : "l"(p));
    return a;
}
__device__ __forceinline__ void cpa16(uint32_t dst, const void* src) {
    asm volatile("cp.async.cg.shared.global [%0], [%1], 16;" :: "r"(dst), "l"(src));
}
#define CP_COMMIT() asm volatile("cp.async.commit_group;" ::: "memory")
#define CP_WAIT(n)  asm volatile("cp.async.wait_group %0;" :: "n"(n) : "memory")

__device__ __forceinline__ void ldm_x4(uint32_t* r, uint32_t addr) {
    asm volatile("ldmatrix.sync.aligned.m8n8.x4.shared.b16 {%0,%1,%2,%3}, [%4];"
        : "=r"(r[0]), "=r"(r[1]), "=r"(r[2]), "=r"(r[3]) : "r"(addr));
}
// int8 tensor-core mma: s8 x s8 -> s32, 2x HMMA rate
__device__ __forceinline__ void mma16832(int* d, const uint32_t* a, uint32_t b0, uint32_t b1) {
    asm volatile(
        "mma.sync.aligned.m16n8k32.row.col.s32.s8.s8.s32 "
        "{%0,%1,%2,%3}, {%4,%5,%6,%7}, {%8,%9}, {%0,%1,%2,%3};"
        : "+r"(d[0]), "+r"(d[1]), "+r"(d[2]), "+r"(d[3])
        : "r"(a[0]), "r"(a[1]), "r"(a[2]), "r"(a[3]), "r"(b0), "r"(b1));
}

// ======================================================================
// Kernel 0: per-row symmetric int8 quantization (one warp per row)
// ======================================================================
__global__ __launch_bounds__(256)
void quant_kernel(const float* __restrict__ src, int8_t* __restrict__ dst,
                  float* __restrict__ scales, int nrows) {
    const int warp = blockIdx.x * 8 + (threadIdx.x >> 5);
    const int lid = threadIdx.x & 31;
    if (warp >= nrows) return;
    const float4* s4 = (const float4*)(src + (size_t)warp * DIN);
    float4 v[6];
    float m = 0.f;
#pragma unroll
    for (int i = 0; i < 6; i++) {
        v[i] = s4[lid + i * 32];
        m = fmaxf(m, fmaxf(fmaxf(fabsf(v[i].x), fabsf(v[i].y)),
                           fmaxf(fabsf(v[i].z), fabsf(v[i].w))));
    }
#pragma unroll
    for (int off = 16; off > 0; off >>= 1)
        m = fmaxf(m, __shfl_xor_sync(0xffffffffu, m, off));
    const float inv = (m > 0.f) ? 127.f / m : 0.f;
    if (lid == 0) scales[warp] = (m > 0.f) ? m / 127.f : 1.f;
    char4* d4 = (char4*)(dst + (size_t)warp * DIN);
#pragma unroll
    for (int i = 0; i < 6; i++) {
        char4 c;
        c.x = (char)__float2int_rn(v[i].x * inv);
        c.y = (char)__float2int_rn(v[i].y * inv);
        c.z = (char)__float2int_rn(v[i].z * inv);
        c.w = (char)__float2int_rn(v[i].w * inv);
        d4[lid + i * 32] = c;
    }
}

// ======================================================================
// Kernel 1: transpose W_dec [DIN, DH] -> g_wdth [DH, DIN]  (fp16)
// ======================================================================
__global__ void transpose_wdec(const float* __restrict__ wdec) {
    __shared__ float tile[32][33];
    const int h0 = blockIdx.x * 32;
    const int i0 = blockIdx.y * 32;
#pragma unroll
    for (int j = 0; j < 32; j += 8)
        tile[threadIdx.y + j][threadIdx.x] =
            wdec[(size_t)(i0 + threadIdx.y + j) * DH + (h0 + threadIdx.x)];
    __syncthreads();
#pragma unroll
    for (int j = 0; j < 32; j += 8)
        g_wdth[(size_t)(h0 + threadIdx.y + j) * DIN + (i0 + threadIdx.x)] =
            __float2half(tile[threadIdx.x][threadIdx.y + j]);
}

// ======================================================================
// Kernel 2: IMMA int8 encode GEMM  z = relu(sx*sw*(X8 @ W8^T) + b) -> bf16
//   Byte-isomorphic to the proven R7 bf16 kernel: BM=BN=128, 64B k-slab
//   per row per iter (now k=64 int8), PITCH=80 conflict-free, 3-stage
//   cp.async, 8 warps 4(m) x 2(n), warp tile 32x64, m16n8k32 s8 mma.
//   NKB = 12 (half of bf16's 24) at 2x per-instruction k -> ~2x mainloop.
// ======================================================================
#define KBYTES 64
#define PITCH 80
#define NKB (DIN / KBYTES)               // 12
#define STG_BYTES (128 * PITCH)          // 10240 per tile
#define STAGE_BYTES (2 * STG_BYTES)      // A + B = 20480
#define ENC_SMEM (3 * STAGE_BYTES + 2048) // 63488

__device__ __forceinline__ void enc_load(char* sA, char* sB,
                                         const int8_t* __restrict__ X,
                                         const int8_t* __restrict__ W,
                                         int bm, int bn, int kc, int tid) {
    const int k0 = kc * KBYTES;
#pragma unroll
    for (int i = 0; i < 2; i++) {
        const int cid = tid + i * 256;          // 512 chunks: 128 rows x 4 x 16B
        const int r = cid >> 2, c = (cid & 3) * 16;
        cpa16(smem_u32(sA + r * PITCH + c), &X[(size_t)(bm + r) * DIN + k0 + c]);
        cpa16(smem_u32(sB + r * PITCH + c), &W[(size_t)(bn + r) * DIN + k0 + c]);
    }
    CP_COMMIT();
}

__global__ __launch_bounds__(256, 2)
void encode_mma(const int8_t* __restrict__ X, const int8_t* __restrict__ W,
                const float* __restrict__ benc) {
    extern __shared__ __align__(16) char smem[];
    float* sbias = (float*)(smem + 3 * STAGE_BYTES);
    float* ssw   = sbias + 128;

    const int tid = threadIdx.x;
    const int lane = tid & 31;
    const int wid = tid >> 5;
    const int warp_m = wid & 3;
    const int warp_n = wid >> 2;
    const int bm = blockIdx.y * 128;
    const int bn = blockIdx.x * 128;

    if (tid < 128) {
        sbias[tid] = benc[bn + tid];
        ssw[tid]   = g_sw[bn + tid];
    }

    int d[2][8][4];
#pragma unroll
    for (int mt = 0; mt < 2; mt++)
#pragma unroll
        for (int nt = 0; nt < 8; nt++)
#pragma unroll
            for (int q = 0; q < 4; q++) d[mt][nt][q] = 0;

    const int a_row = warp_m * 32 + (lane & 15);
    const int a_kb  = ((lane >> 4) & 1) * 16;
    const int b_row = warp_n * 64 + (lane & 7) + ((lane >> 4) << 3);
    const int b_kb  = ((lane >> 3) & 1) * 16;

    enc_load(smem + 0 * STAGE_BYTES, smem + 0 * STAGE_BYTES + STG_BYTES, X, W, bm, bn, 0, tid);
    enc_load(smem + 1 * STAGE_BYTES, smem + 1 * STAGE_BYTES + STG_BYTES, X, W, bm, bn, 1, tid);

    int cur = 0, nxt2 = 2;
    for (int kb = 0; kb < NKB; kb++) {
        if (kb >= NKB - 1) { CP_WAIT(0); } else { CP_WAIT(1); }
        __syncthreads();   // stage cur ready; stage nxt2 free for reuse

        if (kb + 2 < NKB) {
            char* base = smem + nxt2 * STAGE_BYTES;
            enc_load(base, base + STG_BYTES, X, W, bm, bn, kb + 2, tid);
        }

        char* cA = smem + cur * STAGE_BYTES;
        char* cB = cA + STG_BYTES;
#pragma unroll
        for (int s = 0; s < 2; s++) {          // two k32 steps per 64B chunk
            uint32_t a[2][4], b[4][4];
#pragma unroll
            for (int mt = 0; mt < 2; mt++)
                ldm_x4(a[mt], smem_u32(cA + (a_row + mt * 16) * PITCH + s * 32 + a_kb));
#pragma unroll
            for (int p = 0; p < 4; p++)
                ldm_x4(b[p], smem_u32(cB + (b_row + p * 16) * PITCH + s * 32 + b_kb));
#pragma unroll
            for (int mt = 0; mt < 2; mt++)
#pragma unroll
                for (int p = 0; p < 4; p++) {
                    mma16832(d[mt][2 * p],     a[mt], b[p][0], b[p][1]);
                    mma16832(d[mt][2 * p + 1], a[mt], b[p][2], b[p][3]);
                }
        }
        cur = (cur + 1) % 3;
        nxt2 = (nxt2 + 1) % 3;
    }

    // epilogue: dequant + bias + relu + bf16 store
#pragma unroll
    for (int mt = 0; mt < 2; mt++) {
        const int r0 = bm + warp_m * 32 + mt * 16 + (lane >> 2);
        const float sxa = g_sx[r0];
        const float sxb = g_sx[r0 + 8];
#pragma unroll
        for (int nt = 0; nt < 8; nt++) {
            const int cl = warp_n * 64 + nt * 8 + (lane & 3) * 2;
            const float w0 = ssw[cl], w1 = ssw[cl + 1];
            const float b0 = sbias[cl], b1 = sbias[cl + 1];
            const __nv_bfloat162 v0 = __floats2bfloat162_rn(
                fmaxf(fmaf((float)d[mt][nt][0], sxa * w0, b0), 0.f),
                fmaxf(fmaf((float)d[mt][nt][1], sxa * w1, b1), 0.f));
            const __nv_bfloat162 v1 = __floats2bfloat162_rn(
                fmaxf(fmaf((float)d[mt][nt][2], sxb * w0, b0), 0.f),
                fmaxf(fmaf((float)d[mt][nt][3], sxb * w1, b1), 0.f));
            *(__nv_bfloat162*)&g_zb[(size_t)r0 * DH + bn + cl]       = v0;
            *(__nv_bfloat162*)&g_zb[(size_t)(r0 + 8) * DH + bn + cl] = v1;
        }
    }
}

// ======================================================================
// Kernel 3: histogram candidate select on bf16 z. One CTA per row.
// (R8-proven config.) Bin = bf16-bits >> 2; element index = u*8 + w*2.
// ======================================================================
__global__ __launch_bounds__(256)
void hist_kernel() {
    const int row = blockIdx.x;
    const int tid = threadIdx.x;
    __shared__ uint32_t hist[NBIN];
    __shared__ uint32_t gsum[256];
    __shared__ uint32_t s_cut;
    __shared__ uint32_t s_cnt;

    for (int i = tid; i < NBIN; i += 256) hist[i] = 0;
    if (tid == 0) s_cnt = 0;
    __syncthreads();

    const uint4* z4 = (const uint4*)&g_zb[(size_t)row * DH];
    uint32_t v[32];
#pragma unroll
    for (int j = 0; j < 8; j++) {
        const uint4 t = z4[tid + j * 256];
        v[j * 4 + 0] = t.x; v[j * 4 + 1] = t.y; v[j * 4 + 2] = t.z; v[j * 4 + 3] = t.w;
    }
#pragma unroll
    for (int j = 0; j < 32; j++) {
        const uint32_t lo = v[j] & 0xffffu;
        const uint32_t hi = v[j] >> 16;
        if (lo && lo < 0x8000u) atomicAdd(&hist[lo >> 2], 1u);
        if (hi && hi < 0x8000u) atomicAdd(&hist[hi >> 2], 1u);
    }
    __syncthreads();

    uint32_t s = 0;
#pragma unroll
    for (int q = 0; q < NBIN / 256; q++) s += hist[tid * (NBIN / 256) + q];
    gsum[tid] = s;
    __syncthreads();

    if (tid == 0) {
        uint32_t cum = 0; int g = 255;
        for (; g >= 0; --g) {
            if (cum + gsum[g] >= CUMTGT) break;
            cum += gsum[g];
        }
        uint32_t cut = 1;   // g < 0: take every positive value
        if (g >= 0) {
            const int gb = NBIN / 256;
            int b = g * gb + gb - 1; uint32_t c2 = cum;
            for (; b > g * gb; --b) { c2 += hist[b]; if (c2 >= CUMTGT) break; }
            cut = ((uint32_t)b) << 2;
            if (cut == 0) cut = 1;
        }
        s_cut = cut;
    }
    __syncthreads();

    const uint32_t cut = s_cut;
#pragma unroll
    for (int j = 0; j < 32; j++) {
        const int u = tid + (j >> 2) * 256;     // uint4 index within row
        const int base = u * 8 + (j & 3) * 2;   // bf16 element index
        const uint32_t lo = v[j] & 0xffffu;
        const uint32_t hi = v[j] >> 16;
        if (lo < 0x8000u && lo >= cut) {
            const int p = atomicAdd(&s_cnt, 1u);
            if (p < CMAX) g_candi[(size_t)row * CMAX + p] = base;
        }
        if (hi < 0x8000u && hi >= cut) {
            const int p = atomicAdd(&s_cnt, 1u);
            if (p < CMAX) g_candi[(size_t)row * CMAX + p] = base + 1;
        }
    }
    __syncthreads();
    if (tid == 0) g_candcnt[row] = (s_cnt < CMAX) ? (int)s_cnt : CMAX;
}

// ======================================================================
// Kernel 4: fused refine (compensated-fp32 double-float, ~1e-11 rel)
// + exact top-32 selection + sparse fp16 decode. One CTA (256 thr) per
// row. (R8-proven structure; fp16 W_dec^T halves decode traffic.)
// ======================================================================
__global__ __launch_bounds__(256)
void refine_decode(const float* __restrict__ X, const float* __restrict__ W,
                   const float* __restrict__ benc,
                   const float* __restrict__ bdec, float* __restrict__ out) {
    const int row = blockIdx.x;
    const int tid = threadIdx.x;
    const int wid = tid >> 5;
    const int lid = tid & 31;

    __shared__ float  xs[DIN];
    __shared__ double dv[CMAX];
    __shared__ int    ci[CMAX];
    __shared__ int    kept[CMAX];
    __shared__ float  sv[TK];
    __shared__ int    si[TK];

    const int cnt = g_candcnt[row];
    for (int k = tid; k < DIN; k += 256) xs[k] = X[(size_t)row * DIN + k];
    for (int c = tid; c < cnt; c += 256) ci[c] = g_candi[(size_t)row * CMAX + c];
    if (tid < TK) { sv[tid] = 0.f; si[tid] = 0; }
    __syncthreads();

    // double-float dot per candidate (warp-per-candidate)
    for (int c = wid; c < cnt; c += 8) {
        const int h = ci[c];
        const float* w = &W[(size_t)h * DIN];
        float hi = 0.f, lo = 0.f;
#pragma unroll 4
        for (int k = lid; k < DIN; k += 32) {
            const float a = xs[k], b = w[k];
            const float p = a * b;
            const float e = fmaf(a, b, -p);
            const float t = hi + p;
            const float bb = t - hi;
            const float err = (hi - (t - bb)) + (p - bb);
            hi = t;
            lo += e + err;
        }
#pragma unroll
        for (int off = 16; off > 0; off >>= 1) {
            const float oh = __shfl_down_sync(0xffffffffu, hi, off);
            const float ol = __shfl_down_sync(0xffffffffu, lo, off);
            const float t = hi + oh;
            const float bb = t - hi;
            const float err = (hi - (t - bb)) + (oh - bb);
            hi = t;
            lo += ol + err;
        }
        if (lid == 0) {
            const float be = benc[h];
            const float t = hi + be;
            const float bb = t - hi;
            const float err = (hi - (t - bb)) + (be - bb);
            double acc = (double)t + (double)(lo + err);
            dv[c] = acc > 0.0 ? acc : 0.0;
        }
    }
    __syncthreads();

    // exact rank (ties by lower index)
    for (int c = tid; c < cnt; c += 256) {
        const double vi = dv[c]; const int ii = ci[c];
        int rank = 0;
        for (int j = 0; j < cnt; j++) {
            const double vj = dv[j];
            rank += (vj > vi || (vj == vi && ci[j] < ii)) ? 1 : 0;
        }
        kept[c] = (rank < TK) ? 1 : 0;
    }
    __syncthreads();

    // compact kept in ascending hidden-index order -> smem sv/si
    for (int c = tid; c < cnt; c += 256) {
        if (kept[c]) {
            const int ii = ci[c];
            int slot = 0;
            for (int j = 0; j < cnt; j++)
                if (kept[j] && ci[j] < ii) slot++;
            if (slot < TK) { sv[slot] = (float)dv[c]; si[slot] = ii; }
        }
    }
    __syncthreads();

    // sparse decode with fp16 W_dec^T: 3 cols/thread
    float acc0 = bdec[tid];
    float acc1 = bdec[tid + 256];
    float acc2 = bdec[tid + 512];
#pragma unroll 8
    for (int k = 0; k < TK; k++) {
        const float vv = sv[k];
        const __half* w = &g_wdth[(size_t)si[k] * DIN];
        acc0 = fmaf(vv, __half2float(w[tid]),       acc0);
        acc1 = fmaf(vv, __half2float(w[tid + 256]), acc1);
        acc2 = fmaf(vv, __half2float(w[tid + 512]), acc2);
    }
    float* o = &out[(size_t)row * DIN];
    o[tid]       = acc0;
    o[tid + 256] = acc1;
    o[tid + 512] = acc2;
}

// ======================================================================
// launch
// ======================================================================
extern "C" void kernel_launch(void* const* d_in, const int* in_sizes, int n_in,
                              void* d_out, int out_size) {
    const float* x     = (const float*)d_in[0];   // [8192, 768]
    const float* w_enc = (const float*)d_in[1];   // [16384, 768]
    const float* b_enc = (const float*)d_in[2];   // [16384]
    const float* w_dec = (const float*)d_in[3];   // [768, 16384]
    const float* b_dec = (const float*)d_in[4];   // [768]
    float* out = (float*)d_out;                   // [8192, 768]

    static int enc_attr_set = 0;
    if (!enc_attr_set) {
        cudaFuncSetAttribute(encode_mma, cudaFuncAttributeMaxDynamicSharedMemorySize, ENC_SMEM);
        enc_attr_set = 1;
    }

    // 0. per-row int8 quantization of X and W_enc
    int8_t* x8; cudaGetSymbolAddress((void**)&x8, g_x8);
    int8_t* w8; cudaGetSymbolAddress((void**)&w8, g_w8);
    float* sx; cudaGetSymbolAddress((void**)&sx, g_sx);
    float* sw; cudaGetSymbolAddress((void**)&sw, g_sw);
    quant_kernel<<<BATCH / 8, 256>>>(x, x8, sx, BATCH);
    quant_kernel<<<DH / 8, 256>>>(w_enc, w8, sw, DH);

    // 1. transpose W_dec -> fp16 (coalesced decode gathers, half traffic)
    {
        dim3 grid(DH / 32, DIN / 32);
        dim3 block(32, 8);
        transpose_wdec<<<grid, block>>>(w_dec);
    }
    // 2. IMMA int8 encode GEMM + dequant + bias + relu
    {
        dim3 grid(DH / 128, BATCH / 128);
        encode_mma<<<grid, 256, ENC_SMEM>>>(x8, w8, b_enc);
    }
    // 3. per-row candidate capture (standalone, R8-proven)
    hist_kernel<<<BATCH, 256>>>();
    // 4. fused refine + exact top-32 + sparse fp16 decode (R8-proven)
    refine_decode<<<BATCH, 256>>>(x, w_enc, b_enc, b_dec, out);
}

// round 13
// speedup vs baseline: 1.4519x; 1.4519x over previous
#include <cuda_runtime.h>
#include <cuda_bf16.h>
#include <cuda_fp16.h>
#include <cstdint>
#include <climits>

#define BATCH 8192
#define DIN   768
#define DH    16384
#define TK    32
#define CMAX  448
#define NBIN  8192          // bf16-bits >> 2
#define CUMTGT 48
#define NCHUNK 4
#define CROWS (BATCH / NCHUNK)   // 2048

// ---- scratch (static device globals; no dynamic allocation) ----
__device__ __nv_bfloat16 g_zb[(size_t)BATCH * DH];   // 256 MB post-relu activations (bf16)
__device__ __half g_wdth[(size_t)DH * DIN];          // 24 MB transposed W_dec (fp16)
__device__ __nv_bfloat16 g_xbf[(size_t)BATCH * DIN];
__device__ __nv_bfloat16 g_wbf[(size_t)DH * DIN];
__device__ int    g_candi[(size_t)BATCH * CMAX];
__device__ int    g_candcnt[BATCH];

// ======================================================================
// helpers (all target-independent PTX: cp.async, ldmatrix, mma.sync)
// ======================================================================
__device__ __forceinline__ uint32_t smem_u32(const void* p) {
    uint32_t a;
    asm("{ .reg .u64 t; cvta.to.shared.u64 t, %1; cvt.u32.u64 %0, t; }" : "=r"(a) : "l"(p));
    return a;
}
__device__ __forceinline__ void cpa16(uint32_t dst, const void* src) {
    asm volatile("cp.async.cg.shared.global [%0], [%1], 16;" :: "r"(dst), "l"(src));
}
#define CP_COMMIT() asm volatile("cp.async.commit_group;" ::: "memory")
#define CP_WAIT(n)  asm volatile("cp.async.wait_group %0;" :: "n"(n) : "memory")

__device__ __forceinline__ void ldm_x4(uint32_t* r, uint32_t addr) {
    asm volatile("ldmatrix.sync.aligned.m8n8.x4.shared.b16 {%0,%1,%2,%3}, [%4];"
        : "=r"(r[0]), "=r"(r[1]), "=r"(r[2]), "=r"(r[3]) : "r"(addr));
}
__device__ __forceinline__ void mma16816(float* d, const uint32_t* a, uint32_t b0, uint32_t b1) {
    asm volatile(
        "mma.sync.aligned.m16n8k16.row.col.f32.bf16.bf16.f32 "
        "{%0,%1,%2,%3}, {%4,%5,%6,%7}, {%8,%9}, {%0,%1,%2,%3};"
        : "+f"(d[0]), "+f"(d[1]), "+f"(d[2]), "+f"(d[3])
        : "r"(a[0]), "r"(a[1]), "r"(a[2]), "r"(a[3]), "r"(b0), "r"(b1));
}

// ======================================================================
// Kernel 0: fp32 -> bf16 conversion (vectorized)
// ======================================================================
__global__ void cvt_bf16_kernel(const float* __restrict__ s, __nv_bfloat16* __restrict__ d, int n4) {
    const int i = blockIdx.x * 256 + threadIdx.x;
    if (i < n4) {
        const float4 v = ((const float4*)s)[i];
        ((__nv_bfloat162*)d)[i * 2 + 0] = __floats2bfloat162_rn(v.x, v.y);
        ((__nv_bfloat162*)d)[i * 2 + 1] = __floats2bfloat162_rn(v.z, v.w);
    }
}

// ======================================================================
// Kernel 1: transpose W_dec [DIN, DH] -> g_wdth [DH, DIN]  (fp16)
// ======================================================================
__global__ void transpose_wdec(const float* __restrict__ wdec) {
    __shared__ float tile[32][33];
    const int h0 = blockIdx.x * 32;
    const int i0 = blockIdx.y * 32;
#pragma unroll
    for (int j = 0; j < 32; j += 8)
        tile[threadIdx.y + j][threadIdx.x] =
            wdec[(size_t)(i0 + threadIdx.y + j) * DH + (h0 + threadIdx.x)];
    __syncthreads();
#pragma unroll
    for (int j = 0; j < 32; j += 8)
        g_wdth[(size_t)(h0 + threadIdx.y + j) * DIN + (i0 + threadIdx.x)] =
            __float2half(tile[threadIdx.x][threadIdx.y + j]);
}

// ======================================================================
// Kernel 2: HMMA bf16 encode GEMM  z = relu(X @ W^T + b) -> bf16
//   R7 config (best measured, 3x confirmed): BM=BN=128, BK=32, 3-stage
//   cp.async, PITCH=80 conflict-free, 8 warps 4(m) x 2(n), 32x64 warp
//   tile, 128 regs/thread -> 2 CTAs/SM. Chunked by row_base.
// ======================================================================
#define EBK 32
#define PITCH 80
#define NKB (DIN / EBK)                  // 24
#define STG_BYTES (128 * PITCH)          // 10240 per tile
#define STAGE_BYTES (2 * STG_BYTES)      // A + B = 20480
#define ENC_SMEM (3 * STAGE_BYTES + 512) // 61952

__device__ __forceinline__ void enc_load(char* sA, char* sB,
                                         const __nv_bfloat16* __restrict__ X,
                                         const __nv_bfloat16* __restrict__ W,
                                         int bm, int bn, int kc, int tid) {
    const int k0 = kc * EBK;
#pragma unroll
    for (int i = 0; i < 2; i++) {
        const int cid = tid + i * 256;          // 512 chunks: 128 rows x 4 x 16B
        const int r = cid >> 2, c = cid & 3;
        cpa16(smem_u32(sA + r * PITCH + c * 16), &X[(size_t)(bm + r) * DIN + k0 + c * 8]);
        cpa16(smem_u32(sB + r * PITCH + c * 16), &W[(size_t)(bn + r) * DIN + k0 + c * 8]);
    }
    CP_COMMIT();
}

__global__ __launch_bounds__(256, 2)
void encode_mma(const __nv_bfloat16* __restrict__ X, const __nv_bfloat16* __restrict__ W,
                const float* __restrict__ benc, int row_base) {
    extern __shared__ __align__(16) char smem[];
    float* sbias = (float*)(smem + 3 * STAGE_BYTES);

    const int tid = threadIdx.x;
    const int lane = tid & 31;
    const int wid = tid >> 5;
    const int warp_m = wid & 3;
    const int warp_n = wid >> 2;
    const int bm = row_base + blockIdx.y * 128;
    const int bn = blockIdx.x * 128;

    if (tid < 128) sbias[tid] = benc[bn + tid];

    float d[2][8][4];
#pragma unroll
    for (int mt = 0; mt < 2; mt++)
#pragma unroll
        for (int nt = 0; nt < 8; nt++)
#pragma unroll
            for (int q = 0; q < 4; q++) d[mt][nt][q] = 0.f;

    const int a_row = warp_m * 32 + (lane & 15);
    const int a_kb  = ((lane >> 4) & 1) * 16;
    const int b_row = warp_n * 64 + (lane & 7) + ((lane >> 4) << 3);
    const int b_kb  = ((lane >> 3) & 1) * 16;

    enc_load(smem + 0 * STAGE_BYTES, smem + 0 * STAGE_BYTES + STG_BYTES, X, W, bm, bn, 0, tid);
    enc_load(smem + 1 * STAGE_BYTES, smem + 1 * STAGE_BYTES + STG_BYTES, X, W, bm, bn, 1, tid);

    int cur = 0, nxt2 = 2;
    for (int kb = 0; kb < NKB; kb++) {
        if (kb >= NKB - 1) { CP_WAIT(0); } else { CP_WAIT(1); }
        __syncthreads();   // stage cur ready; stage nxt2 free for reuse

        if (kb + 2 < NKB) {
            char* base = smem + nxt2 * STAGE_BYTES;
            enc_load(base, base + STG_BYTES, X, W, bm, bn, kb + 2, tid);
        }

        char* cA = smem + cur * STAGE_BYTES;
        char* cB = cA + STG_BYTES;
#pragma unroll
        for (int s = 0; s < 2; s++) {          // two k16 steps per 32-chunk
            uint32_t a[2][4], b[4][4];
#pragma unroll
            for (int mt = 0; mt < 2; mt++)
                ldm_x4(a[mt], smem_u32(cA + (a_row + mt * 16) * PITCH + s * 32 + a_kb));
#pragma unroll
            for (int p = 0; p < 4; p++)
                ldm_x4(b[p], smem_u32(cB + (b_row + p * 16) * PITCH + s * 32 + b_kb));
#pragma unroll
            for (int mt = 0; mt < 2; mt++)
#pragma unroll
                for (int p = 0; p < 4; p++) {
                    mma16816(d[mt][2 * p],     a[mt], b[p][0], b[p][1]);
                    mma16816(d[mt][2 * p + 1], a[mt], b[p][2], b[p][3]);
                }
        }
        cur = (cur + 1) % 3;
        nxt2 = (nxt2 + 1) % 3;
    }

    // epilogue: bias + relu + bf16 store
#pragma unroll
    for (int mt = 0; mt < 2; mt++) {
        const int r0 = bm + warp_m * 32 + mt * 16 + (lane >> 2);
#pragma unroll
        for (int nt = 0; nt < 8; nt++) {
            const int cl = warp_n * 64 + nt * 8 + (lane & 3) * 2;
            const float b0 = sbias[cl], b1 = sbias[cl + 1];
            const __nv_bfloat162 v0 = __floats2bfloat162_rn(
                fmaxf(d[mt][nt][0] + b0, 0.f), fmaxf(d[mt][nt][1] + b1, 0.f));
            const __nv_bfloat162 v1 = __floats2bfloat162_rn(
                fmaxf(d[mt][nt][2] + b0, 0.f), fmaxf(d[mt][nt][3] + b1, 0.f));
            *(__nv_bfloat162*)&g_zb[(size_t)r0 * DH + bn + cl]       = v0;
            *(__nv_bfloat162*)&g_zb[(size_t)(r0 + 8) * DH + bn + cl] = v1;
        }
    }
}

// ======================================================================
// Kernel 3: histogram candidate select on bf16 z. One CTA per row.
// ======================================================================
__global__ __launch_bounds__(256)
void hist_kernel(int row_base) {
    const int row = row_base + blockIdx.x;
    const int tid = threadIdx.x;
    __shared__ uint32_t hist[NBIN];
    __shared__ uint32_t gsum[256];
    __shared__ uint32_t s_cut;
    __shared__ uint32_t s_cnt;

    for (int i = tid; i < NBIN; i += 256) hist[i] = 0;
    if (tid == 0) s_cnt = 0;
    __syncthreads();

    const uint4* z4 = (const uint4*)&g_zb[(size_t)row * DH];
    uint32_t v[32];
#pragma unroll
    for (int j = 0; j < 8; j++) {
        const uint4 t = z4[tid + j * 256];
        v[j * 4 + 0] = t.x; v[j * 4 + 1] = t.y; v[j * 4 + 2] = t.z; v[j * 4 + 3] = t.w;
    }
#pragma unroll
    for (int j = 0; j < 32; j++) {
        const uint32_t lo = v[j] & 0xffffu;
        const uint32_t hi = v[j] >> 16;
        if (lo && lo < 0x8000u) atomicAdd(&hist[lo >> 2], 1u);
        if (hi && hi < 0x8000u) atomicAdd(&hist[hi >> 2], 1u);
    }
    __syncthreads();

    uint32_t s = 0;
#pragma unroll
    for (int q = 0; q < NBIN / 256; q++) s += hist[tid * (NBIN / 256) + q];
    gsum[tid] = s;
    __syncthreads();

    if (tid == 0) {
        uint32_t cum = 0; int g = 255;
        for (; g >= 0; --g) {
            if (cum + gsum[g] >= CUMTGT) break;
            cum += gsum[g];
        }
        uint32_t cut = 1;   // g < 0: take every positive value
        if (g >= 0) {
            const int gb = NBIN / 256;
            int b = g * gb + gb - 1; uint32_t c2 = cum;
            for (; b > g * gb; --b) { c2 += hist[b]; if (c2 >= CUMTGT) break; }
            cut = ((uint32_t)b) << 2;
            if (cut == 0) cut = 1;
        }
        s_cut = cut;
    }
    __syncthreads();

    const uint32_t cut = s_cut;
#pragma unroll
    for (int j = 0; j < 32; j++) {
        const int u = tid + (j >> 2) * 256;     // uint4 index within row
        const int base = u * 8 + (j & 3) * 2;   // bf16 element index
        const uint32_t lo = v[j] & 0xffffu;
        const uint32_t hi = v[j] >> 16;
        if (lo < 0x8000u && lo >= cut) {
            const int p = atomicAdd(&s_cnt, 1u);
            if (p < CMAX) g_candi[(size_t)row * CMAX + p] = base;
        }
        if (hi < 0x8000u && hi >= cut) {
            const int p = atomicAdd(&s_cnt, 1u);
            if (p < CMAX) g_candi[(size_t)row * CMAX + p] = base + 1;
        }
    }
    __syncthreads();
    if (tid == 0) g_candcnt[row] = (s_cnt < CMAX) ? (int)s_cnt : CMAX;
}

// ======================================================================
// Kernel 4: fused refine (compensated-fp32 double-float, ~1e-11 rel)
// + exact top-32 selection + sparse fp16 decode. One CTA per row.
// ======================================================================
__global__ __launch_bounds__(256)
void refine_decode(const float* __restrict__ X, const float* __restrict__ W,
                   const float* __restrict__ benc,
                   const float* __restrict__ bdec, float* __restrict__ out,
                   int row_base) {
    const int row = row_base + blockIdx.x;
    const int tid = threadIdx.x;
    const int wid = tid >> 5;
    const int lid = tid & 31;

    __shared__ float  xs[DIN];
    __shared__ double dv[CMAX];
    __shared__ int    ci[CMAX];
    __shared__ int    kept[CMAX];
    __shared__ float  sv[TK];
    __shared__ int    si[TK];

    const int cnt = g_candcnt[row];
    for (int k = tid; k < DIN; k += 256) xs[k] = X[(size_t)row * DIN + k];
    for (int c = tid; c < cnt; c += 256) ci[c] = g_candi[(size_t)row * CMAX + c];
    if (tid < TK) { sv[tid] = 0.f; si[tid] = 0; }
    __syncthreads();

    // double-float dot per candidate (warp-per-candidate)
    for (int c = wid; c < cnt; c += 8) {
        const int h = ci[c];
        const float* w = &W[(size_t)h * DIN];
        float hi = 0.f, lo = 0.f;
#pragma unroll 4
        for (int k = lid; k < DIN; k += 32) {
            const float a = xs[k], b = w[k];
            const float p = a * b;
            const float e = fmaf(a, b, -p);
            const float t = hi + p;
            const float bb = t - hi;
            const float err = (hi - (t - bb)) + (p - bb);
            hi = t;
            lo += e + err;
        }
#pragma unroll
        for (int off = 16; off > 0; off >>= 1) {
            const float oh = __shfl_down_sync(0xffffffffu, hi, off);
            const float ol = __shfl_down_sync(0xffffffffu, lo, off);
            const float t = hi + oh;
            const float bb = t - hi;
            const float err = (hi - (t - bb)) + (oh - bb);
            hi = t;
            lo += ol + err;
        }
        if (lid == 0) {
            const float be = benc[h];
            const float t = hi + be;
            const float bb = t - hi;
            const float err = (hi - (t - bb)) + (be - bb);
            double acc = (double)t + (double)(lo + err);
            dv[c] = acc > 0.0 ? acc : 0.0;
        }
    }
    __syncthreads();

    // exact rank (ties by lower index)
    for (int c = tid; c < cnt; c += 256) {
        const double vi = dv[c]; const int ii = ci[c];
        int rank = 0;
        for (int j = 0; j < cnt; j++) {
            const double vj = dv[j];
            rank += (vj > vi || (vj == vi && ci[j] < ii)) ? 1 : 0;
        }
        kept[c] = (rank < TK) ? 1 : 0;
    }
    __syncthreads();

    // compact kept in ascending hidden-index order -> smem sv/si
    for (int c = tid; c < cnt; c += 256) {
        if (kept[c]) {
            const int ii = ci[c];
            int slot = 0;
            for (int j = 0; j < cnt; j++)
                if (kept[j] && ci[j] < ii) slot++;
            if (slot < TK) { sv[slot] = (float)dv[c]; si[slot] = ii; }
        }
    }
    __syncthreads();

    // sparse decode with fp16 W_dec^T: 3 cols/thread
    float acc0 = bdec[tid];
    float acc1 = bdec[tid + 256];
    float acc2 = bdec[tid + 512];
#pragma unroll 8
    for (int k = 0; k < TK; k++) {
        const float vv = sv[k];
        const __half* w = &g_wdth[(size_t)si[k] * DIN];
        acc0 = fmaf(vv, __half2float(w[tid]),       acc0);
        acc1 = fmaf(vv, __half2float(w[tid + 256]), acc1);
        acc2 = fmaf(vv, __half2float(w[tid + 512]), acc2);
    }
    float* o = &out[(size_t)row * DIN];
    o[tid]       = acc0;
    o[tid + 256] = acc1;
    o[tid + 512] = acc2;
}

// ======================================================================
// launch: software pipeline across two streams.
//   default: cvt, transpose, encode(c) for c = 0..3
//   s2:      hist(c) + refine_decode(c) after encode(c) completes
// Encode (tensor-bound) overlaps tail (memory/latency-bound) of the
// previous chunk; fork/join via events (graph-capture legal).
// ======================================================================
extern "C" void kernel_launch(void* const* d_in, const int* in_sizes, int n_in,
                              void* d_out, int out_size) {
    const float* x     = (const float*)d_in[0];   // [8192, 768]
    const float* w_enc = (const float*)d_in[1];   // [16384, 768]
    const float* b_enc = (const float*)d_in[2];   // [16384]
    const float* w_dec = (const float*)d_in[3];   // [768, 16384]
    const float* b_dec = (const float*)d_in[4];   // [768]
    float* out = (float*)d_out;                   // [8192, 768]

    static cudaStream_t s2;
    static cudaEvent_t ev_enc[NCHUNK];
    static cudaEvent_t ev_tail;
    static int inited = 0;
    if (!inited) {
        cudaStreamCreateWithFlags(&s2, cudaStreamNonBlocking);
        for (int i = 0; i < NCHUNK; i++)
            cudaEventCreateWithFlags(&ev_enc[i], cudaEventDisableTiming);
        cudaEventCreateWithFlags(&ev_tail, cudaEventDisableTiming);
        cudaFuncSetAttribute(encode_mma, cudaFuncAttributeMaxDynamicSharedMemorySize, ENC_SMEM);
        inited = 1;
    }

    __nv_bfloat16* xbf; cudaGetSymbolAddress((void**)&xbf, g_xbf);
    __nv_bfloat16* wbf; cudaGetSymbolAddress((void**)&wbf, g_wbf);

    // preprocessing (default stream)
    {
        const int n4x = BATCH * DIN / 4;
        cvt_bf16_kernel<<<(n4x + 255) / 256, 256>>>(x, xbf, n4x);
        const int n4w = DH * DIN / 4;
        cvt_bf16_kernel<<<(n4w + 255) / 256, 256>>>(w_enc, wbf, n4w);
        dim3 tg(DH / 32, DIN / 32);
        dim3 tb(32, 8);
        transpose_wdec<<<tg, tb>>>(w_dec);
    }

    // pipelined chunks
    for (int c = 0; c < NCHUNK; c++) {
        const int rb = c * CROWS;
        dim3 eg(DH / 128, CROWS / 128);
        encode_mma<<<eg, 256, ENC_SMEM>>>(xbf, wbf, b_enc, rb);
        cudaEventRecord(ev_enc[c], 0);
        cudaStreamWaitEvent(s2, ev_enc[c], 0);
        hist_kernel<<<CROWS, 256, 0, s2>>>(rb);
        refine_decode<<<CROWS, 256, 0, s2>>>(x, w_enc, b_enc, b_dec, out, rb);
    }

    // join side stream back into the origin stream
    cudaEventRecord(ev_tail, s2);
    cudaStreamWaitEvent(0, ev_tail, 0);
}

// round 14
// speedup vs baseline: 1.6457x; 1.1335x over previous
#include <cuda_runtime.h>
#include <cuda_bf16.h>
#include <cuda_fp16.h>
#include <cstdint>
#include <climits>

#define BATCH 8192
#define DIN   768
#define DH    16384
#define TK    32
#define CMAX  512
#define NBIN  8192          // bf16-bits >> 2
#define CUMTGT 44

// ---- scratch (static device globals; no dynamic allocation) ----
__device__ __nv_bfloat16 g_zb[(size_t)BATCH * DH];   // 256 MB post-relu activations (bf16)
__device__ __half g_wdth[(size_t)DH * DIN];          // 24 MB transposed W_dec (fp16)
__device__ __nv_bfloat16 g_xbf[(size_t)BATCH * DIN];
__device__ __nv_bfloat16 g_wbf[(size_t)DH * DIN];
__device__ int   g_candi[(size_t)BATCH * CMAX];
__device__ int   g_candcnt[BATCH];
__device__ float g_selv[BATCH * TK];
__device__ int   g_seli[BATCH * TK];

// ======================================================================
// helpers (all target-independent PTX: cp.async, ldmatrix, mma.sync)
// ======================================================================
__device__ __forceinline__ uint32_t smem_u32(const void* p) {
    uint32_t a;
    asm("{ .reg .u64 t; cvta.to.shared.u64 t, %1; cvt.u32.u64 %0, t; }" : "=r"(a) : "l"(p));
    return a;
}
__device__ __forceinline__ void cpa16(uint32_t dst, const void* src) {
    asm volatile("cp.async.cg.shared.global [%0], [%1], 16;" :: "r"(dst), "l"(src));
}
#define CP_COMMIT() asm volatile("cp.async.commit_group;" ::: "memory")
#define CP_WAIT(n)  asm volatile("cp.async.wait_group %0;" :: "n"(n) : "memory")

__device__ __forceinline__ void ldm_x4(uint32_t* r, uint32_t addr) {
    asm volatile("ldmatrix.sync.aligned.m8n8.x4.shared.b16 {%0,%1,%2,%3}, [%4];"
        : "=r"(r[0]), "=r"(r[1]), "=r"(r[2]), "=r"(r[3]) : "r"(addr));
}
__device__ __forceinline__ void mma16816(float* d, const uint32_t* a, uint32_t b0, uint32_t b1) {
    asm volatile(
        "mma.sync.aligned.m16n8k16.row.col.f32.bf16.bf16.f32 "
        "{%0,%1,%2,%3}, {%4,%5,%6,%7}, {%8,%9}, {%0,%1,%2,%3};"
        : "+f"(d[0]), "+f"(d[1]), "+f"(d[2]), "+f"(d[3])
        : "r"(a[0]), "r"(a[1]), "r"(a[2]), "r"(a[3]), "r"(b0), "r"(b1));
}

// ======================================================================
// Kernel 0: fp32 -> bf16 conversion (vectorized)
// ======================================================================
__global__ void cvt_bf16_kernel(const float* __restrict__ s, __nv_bfloat16* __restrict__ d, int n4) {
    const int i = blockIdx.x * 256 + threadIdx.x;
    if (i < n4) {
        const float4 v = ((const float4*)s)[i];
        ((__nv_bfloat162*)d)[i * 2 + 0] = __floats2bfloat162_rn(v.x, v.y);
        ((__nv_bfloat162*)d)[i * 2 + 1] = __floats2bfloat162_rn(v.z, v.w);
    }
}

// ======================================================================
// Kernel 1: transpose W_dec [DIN, DH] -> g_wdth [DH, DIN]  (fp16)
// ======================================================================
__global__ void transpose_wdec(const float* __restrict__ wdec) {
    __shared__ float tile[32][33];
    const int h0 = blockIdx.x * 32;
    const int i0 = blockIdx.y * 32;
#pragma unroll
    for (int j = 0; j < 32; j += 8)
        tile[threadIdx.y + j][threadIdx.x] =
            wdec[(size_t)(i0 + threadIdx.y + j) * DH + (h0 + threadIdx.x)];
    __syncthreads();
#pragma unroll
    for (int j = 0; j < 32; j += 8)
        g_wdth[(size_t)(h0 + threadIdx.y + j) * DIN + (i0 + threadIdx.x)] =
            __float2half(tile[threadIdx.x][threadIdx.y + j]);
}

// ======================================================================
// Kernel 2: HMMA bf16 encode GEMM  z = relu(X @ W^T + b) -> bf16
//   R7 config (best measured, 4x reproduced at ~648us): BM=BN=128, BK=32,
//   3-stage cp.async, PITCH=80 conflict-free ldmatrix, 8 warps 4(m)x2(n),
//   32x64 warp tile, 128 regs/thread -> 2 CTAs/SM (exact RF packing).
// ======================================================================
#define EBK 32
#define PITCH 80
#define NKB (DIN / EBK)                  // 24
#define STG_BYTES (128 * PITCH)          // 10240 per tile
#define STAGE_BYTES (2 * STG_BYTES)      // A + B = 20480
#define ENC_SMEM (3 * STAGE_BYTES + 512) // 61952

__device__ __forceinline__ void enc_load(char* sA, char* sB,
                                         const __nv_bfloat16* __restrict__ X,
                                         const __nv_bfloat16* __restrict__ W,
                                         int bm, int bn, int kc, int tid) {
    const int k0 = kc * EBK;
#pragma unroll
    for (int i = 0; i < 2; i++) {
        const int cid = tid + i * 256;          // 512 chunks: 128 rows x 4 x 16B
        const int r = cid >> 2, c = cid & 3;
        cpa16(smem_u32(sA + r * PITCH + c * 16), &X[(size_t)(bm + r) * DIN + k0 + c * 8]);
        cpa16(smem_u32(sB + r * PITCH + c * 16), &W[(size_t)(bn + r) * DIN + k0 + c * 8]);
    }
    CP_COMMIT();
}

__global__ __launch_bounds__(256, 2)
void encode_mma(const __nv_bfloat16* __restrict__ X, const __nv_bfloat16* __restrict__ W,
                const float* __restrict__ benc) {
    extern __shared__ __align__(16) char smem[];
    float* sbias = (float*)(smem + 3 * STAGE_BYTES);

    const int tid = threadIdx.x;
    const int lane = tid & 31;
    const int wid = tid >> 5;
    const int warp_m = wid & 3;
    const int warp_n = wid >> 2;
    const int bm = blockIdx.y * 128;
    const int bn = blockIdx.x * 128;

    if (tid < 128) sbias[tid] = benc[bn + tid];

    float d[2][8][4];
#pragma unroll
    for (int mt = 0; mt < 2; mt++)
#pragma unroll
        for (int nt = 0; nt < 8; nt++)
#pragma unroll
            for (int q = 0; q < 4; q++) d[mt][nt][q] = 0.f;

    const int a_row = warp_m * 32 + (lane & 15);
    const int a_kb  = ((lane >> 4) & 1) * 16;
    const int b_row = warp_n * 64 + (lane & 7) + ((lane >> 4) << 3);
    const int b_kb  = ((lane >> 3) & 1) * 16;

    enc_load(smem + 0 * STAGE_BYTES, smem + 0 * STAGE_BYTES + STG_BYTES, X, W, bm, bn, 0, tid);
    enc_load(smem + 1 * STAGE_BYTES, smem + 1 * STAGE_BYTES + STG_BYTES, X, W, bm, bn, 1, tid);

    int cur = 0, nxt2 = 2;
    for (int kb = 0; kb < NKB; kb++) {
        if (kb >= NKB - 1) { CP_WAIT(0); } else { CP_WAIT(1); }
        __syncthreads();   // stage cur ready; stage nxt2 free for reuse

        if (kb + 2 < NKB) {
            char* base = smem + nxt2 * STAGE_BYTES;
            enc_load(base, base + STG_BYTES, X, W, bm, bn, kb + 2, tid);
        }

        char* cA = smem + cur * STAGE_BYTES;
        char* cB = cA + STG_BYTES;
#pragma unroll
        for (int s = 0; s < 2; s++) {          // two k16 steps per 32-chunk
            uint32_t a[2][4], b[4][4];
#pragma unroll
            for (int mt = 0; mt < 2; mt++)
                ldm_x4(a[mt], smem_u32(cA + (a_row + mt * 16) * PITCH + s * 32 + a_kb));
#pragma unroll
            for (int p = 0; p < 4; p++)
                ldm_x4(b[p], smem_u32(cB + (b_row + p * 16) * PITCH + s * 32 + b_kb));
#pragma unroll
            for (int mt = 0; mt < 2; mt++)
#pragma unroll
                for (int p = 0; p < 4; p++) {
                    mma16816(d[mt][2 * p],     a[mt], b[p][0], b[p][1]);
                    mma16816(d[mt][2 * p + 1], a[mt], b[p][2], b[p][3]);
                }
        }
        cur = (cur + 1) % 3;
        nxt2 = (nxt2 + 1) % 3;
    }

    // epilogue: bias + relu + bf16 store
#pragma unroll
    for (int mt = 0; mt < 2; mt++) {
        const int r0 = bm + warp_m * 32 + mt * 16 + (lane >> 2);
#pragma unroll
        for (int nt = 0; nt < 8; nt++) {
            const int cl = warp_n * 64 + nt * 8 + (lane & 3) * 2;
            const float b0 = sbias[cl], b1 = sbias[cl + 1];
            const __nv_bfloat162 v0 = __floats2bfloat162_rn(
                fmaxf(d[mt][nt][0] + b0, 0.f), fmaxf(d[mt][nt][1] + b1, 0.f));
            const __nv_bfloat162 v1 = __floats2bfloat162_rn(
                fmaxf(d[mt][nt][2] + b0, 0.f), fmaxf(d[mt][nt][3] + b1, 0.f));
            *(__nv_bfloat162*)&g_zb[(size_t)r0 * DH + bn + cl]       = v0;
            *(__nv_bfloat162*)&g_zb[(size_t)(r0 + 8) * DH + bn + cl] = v1;
        }
    }
}

// ======================================================================
// Kernel 3: histogram candidate select on bf16 z. One CTA per row.
// Row = 16384 bf16 = 2048 uint4; each thread owns 8 coalesced uint4.
// Bin = bf16-bits >> 2. Element index of word w in uint4 u: u*8 + w*2.
// ======================================================================
__global__ __launch_bounds__(256)
void hist_kernel() {
    const int row = blockIdx.x;
    const int tid = threadIdx.x;
    __shared__ uint32_t hist[NBIN];
    __shared__ uint32_t gsum[256];
    __shared__ uint32_t s_cut;
    __shared__ uint32_t s_cnt;

    for (int i = tid; i < NBIN; i += 256) hist[i] = 0;
    if (tid == 0) s_cnt = 0;
    __syncthreads();

    const uint4* z4 = (const uint4*)&g_zb[(size_t)row * DH];
    uint32_t v[32];
#pragma unroll
    for (int j = 0; j < 8; j++) {
        const uint4 t = z4[tid + j * 256];
        v[j * 4 + 0] = t.x; v[j * 4 + 1] = t.y; v[j * 4 + 2] = t.z; v[j * 4 + 3] = t.w;
    }
#pragma unroll
    for (int j = 0; j < 32; j++) {
        const uint32_t lo = v[j] & 0xffffu;
        const uint32_t hi = v[j] >> 16;
        if (lo && lo < 0x8000u) atomicAdd(&hist[lo >> 2], 1u);
        if (hi && hi < 0x8000u) atomicAdd(&hist[hi >> 2], 1u);
    }
    __syncthreads();

    uint32_t s = 0;
#pragma unroll
    for (int q = 0; q < NBIN / 256; q++) s += hist[tid * (NBIN / 256) + q];
    gsum[tid] = s;
    __syncthreads();

    if (tid == 0) {
        uint32_t cum = 0; int g = 255;
        for (; g >= 0; --g) {
            if (cum + gsum[g] >= CUMTGT) break;
            cum += gsum[g];
        }
        uint32_t cut = 1;   // g < 0: take every positive value
        if (g >= 0) {
            const int gb = NBIN / 256;
            int b = g * gb + gb - 1; uint32_t c2 = cum;
            for (; b > g * gb; --b) { c2 += hist[b]; if (c2 >= CUMTGT) break; }
            cut = ((uint32_t)b) << 2;
            if (cut == 0) cut = 1;
        }
        s_cut = cut;
    }
    __syncthreads();

    const uint32_t cut = s_cut;
#pragma unroll
    for (int j = 0; j < 32; j++) {
        const int u = tid + (j >> 2) * 256;     // uint4 index within row
        const int base = u * 8 + (j & 3) * 2;   // bf16 element index
        const uint32_t lo = v[j] & 0xffffu;
        const uint32_t hi = v[j] >> 16;
        if (lo < 0x8000u && lo >= cut) {
            const int p = atomicAdd(&s_cnt, 1u);
            if (p < CMAX) g_candi[(size_t)row * CMAX + p] = base;
        }
        if (hi < 0x8000u && hi >= cut) {
            const int p = atomicAdd(&s_cnt, 1u);
            if (p < CMAX) g_candi[(size_t)row * CMAX + p] = base + 1;
        }
    }
    __syncthreads();
    if (tid == 0) g_candcnt[row] = (s_cnt < CMAX) ? (int)s_cnt : CMAX;
}

// ======================================================================
// Kernel 4: refine (compensated-fp32 double-float, ~1e-11 rel) + exact
// top-32 selection. One CTA (256 thr) per row. (R7-proven structure.)
// ======================================================================
__global__ __launch_bounds__(256)
void refine_kernel(const float* __restrict__ X, const float* __restrict__ W,
                   const float* __restrict__ benc) {
    const int row = blockIdx.x;
    const int tid = threadIdx.x;
    const int wid = tid >> 5;
    const int lid = tid & 31;

    __shared__ float  xs[DIN];
    __shared__ double dv[CMAX];
    __shared__ int    ci[CMAX];
    __shared__ int    kept[CMAX];

    const int cnt = g_candcnt[row];
    for (int k = tid; k < DIN; k += 256) xs[k] = X[(size_t)row * DIN + k];
    for (int c = tid; c < cnt; c += 256) ci[c] = g_candi[(size_t)row * CMAX + c];
    if (tid < TK) { g_selv[row * TK + tid] = 0.f; g_seli[row * TK + tid] = 0; }
    __syncthreads();

    // double-float dot per candidate (warp-per-candidate)
    for (int c = wid; c < cnt; c += 8) {
        const int h = ci[c];
        const float* w = &W[(size_t)h * DIN];
        float hi = 0.f, lo = 0.f;
#pragma unroll 4
        for (int k = lid; k < DIN; k += 32) {
            const float a = xs[k], b = w[k];
            const float p = a * b;
            const float e = fmaf(a, b, -p);
            const float t = hi + p;
            const float bb = t - hi;
            const float err = (hi - (t - bb)) + (p - bb);
            hi = t;
            lo += e + err;
        }
#pragma unroll
        for (int off = 16; off > 0; off >>= 1) {
            const float oh = __shfl_down_sync(0xffffffffu, hi, off);
            const float ol = __shfl_down_sync(0xffffffffu, lo, off);
            const float t = hi + oh;
            const float bb = t - hi;
            const float err = (hi - (t - bb)) + (oh - bb);
            hi = t;
            lo += ol + err;
        }
        if (lid == 0) {
            const float be = benc[h];
            const float t = hi + be;
            const float bb = t - hi;
            const float err = (hi - (t - bb)) + (be - bb);
            double acc = (double)t + (double)(lo + err);
            dv[c] = acc > 0.0 ? acc : 0.0;
        }
    }
    __syncthreads();

    // exact rank (ties by lower index)
    for (int c = tid; c < cnt; c += 256) {
        const double vi = dv[c]; const int ii = ci[c];
        int rank = 0;
        for (int j = 0; j < cnt; j++) {
            const double vj = dv[j];
            rank += (vj > vi || (vj == vi && ci[j] < ii)) ? 1 : 0;
        }
        kept[c] = (rank < TK) ? 1 : 0;
    }
    __syncthreads();

    // compact kept in ascending hidden-index order
    for (int c = tid; c < cnt; c += 256) {
        if (kept[c]) {
            const int ii = ci[c];
            int slot = 0;
            for (int j = 0; j < cnt; j++)
                if (kept[j] && ci[j] < ii) slot++;
            if (slot < TK) {
                g_selv[row * TK + slot] = (float)dv[c];
                g_seli[row * TK + slot] = ii;
            }
        }
    }
}

// ======================================================================
// Kernel 5: sparse decode  out[b,:] = b_dec + sum_k v_k * WdT16[idx_k, :]
// fp16 W_dec^T halves the gather traffic (786 -> 393 MB).
// ======================================================================
__global__ __launch_bounds__(256)
void decode_kernel(const float* __restrict__ bdec, float* __restrict__ out) {
    const int row = blockIdx.x;
    const int tid = threadIdx.x;
    __shared__ float sv[TK];
    __shared__ int   si[TK];
    if (tid < TK) {
        sv[tid] = g_selv[row * TK + tid];
        si[tid] = g_seli[row * TK + tid];
    }
    __syncthreads();

    float acc0 = bdec[tid];
    float acc1 = bdec[tid + 256];
    float acc2 = bdec[tid + 512];
#pragma unroll 8
    for (int k = 0; k < TK; k++) {
        const float vv = sv[k];
        const __half* w = &g_wdth[(size_t)si[k] * DIN];
        acc0 = fmaf(vv, __half2float(w[tid]),       acc0);
        acc1 = fmaf(vv, __half2float(w[tid + 256]), acc1);
        acc2 = fmaf(vv, __half2float(w[tid + 512]), acc2);
    }
    float* o = &out[(size_t)row * DIN];
    o[tid]       = acc0;
    o[tid + 256] = acc1;
    o[tid + 512] = acc2;
}

// ======================================================================
// launch — linear best-of-breed composition (R7 structure)
// ======================================================================
extern "C" void kernel_launch(void* const* d_in, const int* in_sizes, int n_in,
                              void* d_out, int out_size) {
    const float* x     = (const float*)d_in[0];   // [8192, 768]
    const float* w_enc = (const float*)d_in[1];   // [16384, 768]
    const float* b_enc = (const float*)d_in[2];   // [16384]
    const float* w_dec = (const float*)d_in[3];   // [768, 16384]
    const float* b_dec = (const float*)d_in[4];   // [768]
    float* out = (float*)d_out;                   // [8192, 768]

    static int enc_attr_set = 0;
    if (!enc_attr_set) {
        cudaFuncSetAttribute(encode_mma, cudaFuncAttributeMaxDynamicSharedMemorySize, ENC_SMEM);
        enc_attr_set = 1;
    }

    // 0. bf16 copies of X, W_enc
    __nv_bfloat16* xbf; cudaGetSymbolAddress((void**)&xbf, g_xbf);
    __nv_bfloat16* wbf; cudaGetSymbolAddress((void**)&wbf, g_wbf);
    {
        const int n4x = BATCH * DIN / 4;
        cvt_bf16_kernel<<<(n4x + 255) / 256, 256>>>(x, xbf, n4x);
        const int n4w = DH * DIN / 4;
        cvt_bf16_kernel<<<(n4w + 255) / 256, 256>>>(w_enc, wbf, n4w);
    }
    // 1. transpose W_dec -> fp16
    {
        dim3 grid(DH / 32, DIN / 32);
        dim3 block(32, 8);
        transpose_wdec<<<grid, block>>>(w_dec);
    }
    // 2. HMMA bf16 encode GEMM + bias + relu (R7 config)
    {
        dim3 grid(DH / 128, BATCH / 128);
        encode_mma<<<grid, 256, ENC_SMEM>>>(xbf, wbf, b_enc);
    }
    // 3. per-row candidate capture
    hist_kernel<<<BATCH, 256>>>();
    // 4. exact top-32 via compensated-precision refinement
    refine_kernel<<<BATCH, 256>>>(x, w_enc, b_enc);
    // 5. sparse decode (fp16 W_dec^T)
    decode_kernel<<<BATCH, 256>>>(b_dec, out);
}

// round 15
// speedup vs baseline: 1.7630x; 1.0712x over previous
#include <cuda_runtime.h>
#include <cuda_bf16.h>
#include <cuda_fp16.h>
#include <cstdint>
#include <climits>

#define BATCH 8192
#define DIN   768
#define DH    16384
#define TK    32
#define CMAX  512
#define CUMTGT 44
#define QMIN  64            // only histogram q >= 64 (z >= 0.75)
#define QSCALE (256.0f / 3.0f)

// ---- scratch (static device globals; no dynamic allocation) ----
__device__ uint8_t g_zq[(size_t)BATCH * DH];         // 128 MB quantized z
__device__ __half g_wdth[(size_t)DH * DIN];          // 24 MB transposed W_dec (fp16)
__device__ __nv_bfloat16 g_xbf[(size_t)BATCH * DIN];
__device__ __nv_bfloat16 g_wbf[(size_t)DH * DIN];
__device__ int   g_candi[(size_t)BATCH * CMAX];
__device__ int   g_candcnt[BATCH];
__device__ float g_selv[BATCH * TK];
__device__ int   g_seli[BATCH * TK];

// ======================================================================
// helpers (all target-independent PTX: cp.async, ldmatrix, mma.sync)
// ======================================================================
__device__ __forceinline__ uint32_t smem_u32(const void* p) {
    uint32_t a;
    asm("{ .reg .u64 t; cvta.to.shared.u64 t, %1; cvt.u32.u64 %0, t; }" : "=r"(a) : "l"(p));
    return a;
}
__device__ __forceinline__ void cpa16(uint32_t dst, const void* src) {
    asm volatile("cp.async.cg.shared.global [%0], [%1], 16;" :: "r"(dst), "l"(src));
}
#define CP_COMMIT() asm volatile("cp.async.commit_group;" ::: "memory")
#define CP_WAIT(n)  asm volatile("cp.async.wait_group %0;" :: "n"(n) : "memory")

__device__ __forceinline__ void ldm_x4(uint32_t* r, uint32_t addr) {
    asm volatile("ldmatrix.sync.aligned.m8n8.x4.shared.b16 {%0,%1,%2,%3}, [%4];"
        : "=r"(r[0]), "=r"(r[1]), "=r"(r[2]), "=r"(r[3]) : "r"(addr));
}
__device__ __forceinline__ void mma16816(float* d, const uint32_t* a, uint32_t b0, uint32_t b1) {
    asm volatile(
        "mma.sync.aligned.m16n8k16.row.col.f32.bf16.bf16.f32 "
        "{%0,%1,%2,%3}, {%4,%5,%6,%7}, {%8,%9}, {%0,%1,%2,%3};"
        : "+f"(d[0]), "+f"(d[1]), "+f"(d[2]), "+f"(d[3])
        : "r"(a[0]), "r"(a[1]), "r"(a[2]), "r"(a[3]), "r"(b0), "r"(b1));
}
__device__ __forceinline__ uint8_t quant_z(float z) {
    const float s = fminf(fmaxf(z * QSCALE, 0.f), 255.f);
    return (uint8_t)s;   // truncation: monotone
}

// ======================================================================
// Kernel 0: fp32 -> bf16 conversion (vectorized)
// ======================================================================
__global__ void cvt_bf16_kernel(const float* __restrict__ s, __nv_bfloat16* __restrict__ d, int n4) {
    const int i = blockIdx.x * 256 + threadIdx.x;
    if (i < n4) {
        const float4 v = ((const float4*)s)[i];
        ((__nv_bfloat162*)d)[i * 2 + 0] = __floats2bfloat162_rn(v.x, v.y);
        ((__nv_bfloat162*)d)[i * 2 + 1] = __floats2bfloat162_rn(v.z, v.w);
    }
}

// ======================================================================
// Kernel 1: transpose W_dec [DIN, DH] -> g_wdth [DH, DIN]  (fp16)
// ======================================================================
__global__ void transpose_wdec(const float* __restrict__ wdec) {
    __shared__ float tile[32][33];
    const int h0 = blockIdx.x * 32;
    const int i0 = blockIdx.y * 32;
#pragma unroll
    for (int j = 0; j < 32; j += 8)
        tile[threadIdx.y + j][threadIdx.x] =
            wdec[(size_t)(i0 + threadIdx.y + j) * DH + (h0 + threadIdx.x)];
    __syncthreads();
#pragma unroll
    for (int j = 0; j < 32; j += 8)
        g_wdth[(size_t)(h0 + threadIdx.y + j) * DIN + (i0 + threadIdx.x)] =
            __float2half(tile[threadIdx.x][threadIdx.y + j]);
}

// ======================================================================
// Kernel 2: HMMA bf16 encode GEMM  z = relu(X @ W^T + b) -> uint8 quant
//   R7 config (best measured, 5x reproduced ~646us): BM=BN=128, BK=32,
//   3-stage cp.async, PITCH=80 conflict-free ldmatrix, 8 warps 4(m)x2(n),
//   32x64 warp tile, 128 regs/thread -> 2 CTAs/SM.
// ======================================================================
#define EBK 32
#define PITCH 80
#define NKB (DIN / EBK)                  // 24
#define STG_BYTES (128 * PITCH)          // 10240 per tile
#define STAGE_BYTES (2 * STG_BYTES)      // A + B = 20480
#define ENC_SMEM (3 * STAGE_BYTES + 512) // 61952

__device__ __forceinline__ void enc_load(char* sA, char* sB,
                                         const __nv_bfloat16* __restrict__ X,
                                         const __nv_bfloat16* __restrict__ W,
                                         int bm, int bn, int kc, int tid) {
    const int k0 = kc * EBK;
#pragma unroll
    for (int i = 0; i < 2; i++) {
        const int cid = tid + i * 256;          // 512 chunks: 128 rows x 4 x 16B
        const int r = cid >> 2, c = cid & 3;
        cpa16(smem_u32(sA + r * PITCH + c * 16), &X[(size_t)(bm + r) * DIN + k0 + c * 8]);
        cpa16(smem_u32(sB + r * PITCH + c * 16), &W[(size_t)(bn + r) * DIN + k0 + c * 8]);
    }
    CP_COMMIT();
}

__global__ __launch_bounds__(256, 2)
void encode_mma(const __nv_bfloat16* __restrict__ X, const __nv_bfloat16* __restrict__ W,
                const float* __restrict__ benc) {
    extern __shared__ __align__(16) char smem[];
    float* sbias = (float*)(smem + 3 * STAGE_BYTES);

    const int tid = threadIdx.x;
    const int lane = tid & 31;
    const int wid = tid >> 5;
    const int warp_m = wid & 3;
    const int warp_n = wid >> 2;
    const int bm = blockIdx.y * 128;
    const int bn = blockIdx.x * 128;

    if (tid < 128) sbias[tid] = benc[bn + tid];

    float d[2][8][4];
#pragma unroll
    for (int mt = 0; mt < 2; mt++)
#pragma unroll
        for (int nt = 0; nt < 8; nt++)
#pragma unroll
            for (int q = 0; q < 4; q++) d[mt][nt][q] = 0.f;

    const int a_row = warp_m * 32 + (lane & 15);
    const int a_kb  = ((lane >> 4) & 1) * 16;
    const int b_row = warp_n * 64 + (lane & 7) + ((lane >> 4) << 3);
    const int b_kb  = ((lane >> 3) & 1) * 16;

    enc_load(smem + 0 * STAGE_BYTES, smem + 0 * STAGE_BYTES + STG_BYTES, X, W, bm, bn, 0, tid);
    enc_load(smem + 1 * STAGE_BYTES, smem + 1 * STAGE_BYTES + STG_BYTES, X, W, bm, bn, 1, tid);

    int cur = 0, nxt2 = 2;
    for (int kb = 0; kb < NKB; kb++) {
        if (kb >= NKB - 1) { CP_WAIT(0); } else { CP_WAIT(1); }
        __syncthreads();   // stage cur ready; stage nxt2 free for reuse

        if (kb + 2 < NKB) {
            char* base = smem + nxt2 * STAGE_BYTES;
            enc_load(base, base + STG_BYTES, X, W, bm, bn, kb + 2, tid);
        }

        char* cA = smem + cur * STAGE_BYTES;
        char* cB = cA + STG_BYTES;
#pragma unroll
        for (int s = 0; s < 2; s++) {          // two k16 steps per 32-chunk
            uint32_t a[2][4], b[4][4];
#pragma unroll
            for (int mt = 0; mt < 2; mt++)
                ldm_x4(a[mt], smem_u32(cA + (a_row + mt * 16) * PITCH + s * 32 + a_kb));
#pragma unroll
            for (int p = 0; p < 4; p++)
                ldm_x4(b[p], smem_u32(cB + (b_row + p * 16) * PITCH + s * 32 + b_kb));
#pragma unroll
            for (int mt = 0; mt < 2; mt++)
#pragma unroll
                for (int p = 0; p < 4; p++) {
                    mma16816(d[mt][2 * p],     a[mt], b[p][0], b[p][1]);
                    mma16816(d[mt][2 * p + 1], a[mt], b[p][2], b[p][3]);
                }
        }
        cur = (cur + 1) % 3;
        nxt2 = (nxt2 + 1) % 3;
    }

    // epilogue: bias + relu + uint8 quantized store (monotone)
#pragma unroll
    for (int mt = 0; mt < 2; mt++) {
        const int r0 = bm + warp_m * 32 + mt * 16 + (lane >> 2);
#pragma unroll
        for (int nt = 0; nt < 8; nt++) {
            const int cl = warp_n * 64 + nt * 8 + (lane & 3) * 2;
            const float b0 = sbias[cl], b1 = sbias[cl + 1];
            uchar2 q0, q1;
            q0.x = quant_z(d[mt][nt][0] + b0);
            q0.y = quant_z(d[mt][nt][1] + b1);
            q1.x = quant_z(d[mt][nt][2] + b0);
            q1.y = quant_z(d[mt][nt][3] + b1);
            *(uchar2*)&g_zq[(size_t)r0 * DH + bn + cl]       = q0;
            *(uchar2*)&g_zq[(size_t)(r0 + 8) * DH + bn + cl] = q1;
        }
    }
}

// ======================================================================
// Kernel 3: 256-bin byte histogram candidate select. One CTA per row.
// Row = 16384 bytes = 1024 uint4; each thread owns 4 coalesced uint4.
// Only q >= QMIN counted (expected ~1590 values >= QMIN per row, 40
// sigma above CUMTGT). Capture = all q >= cut: provably a superset of
// the true top-44 by monotonicity of the quantizer.
// ======================================================================
__global__ __launch_bounds__(256)
void hist_kernel() {
    const int row = blockIdx.x;
    const int tid = threadIdx.x;
    __shared__ uint32_t hist[256];
    __shared__ uint32_t s_cut;
    __shared__ uint32_t s_cnt;

    hist[tid] = 0;
    if (tid == 0) s_cnt = 0;
    __syncthreads();

    const uint4* z4 = (const uint4*)&g_zq[(size_t)row * DH];
    uint32_t v[16];
#pragma unroll
    for (int j = 0; j < 4; j++) {
        const uint4 t = z4[tid + j * 256];
        v[j * 4 + 0] = t.x; v[j * 4 + 1] = t.y; v[j * 4 + 2] = t.z; v[j * 4 + 3] = t.w;
    }
#pragma unroll
    for (int j = 0; j < 16; j++) {
#pragma unroll
        for (int b = 0; b < 4; b++) {
            const uint32_t q = (v[j] >> (8 * b)) & 255u;
            if (q >= QMIN) atomicAdd(&hist[q], 1u);
        }
    }
    __syncthreads();

    if (tid == 0) {
        uint32_t cum = 0; int b = 255;
        for (; b >= QMIN; --b) {
            cum += hist[b];
            if (cum >= CUMTGT) break;
        }
        s_cut = (b < QMIN) ? QMIN : (uint32_t)b;
    }
    __syncthreads();

    const uint32_t cut = s_cut;
#pragma unroll
    for (int j = 0; j < 16; j++) {
        const int u = tid + (j >> 2) * 256;       // uint4 index within row
        const int base = u * 16 + (j & 3) * 4;    // byte (element) index
#pragma unroll
        for (int b = 0; b < 4; b++) {
            const uint32_t q = (v[j] >> (8 * b)) & 255u;
            if (q >= cut) {
                const int p = atomicAdd(&s_cnt, 1u);
                if (p < CMAX) g_candi[(size_t)row * CMAX + p] = base + b;
            }
        }
    }
    __syncthreads();
    if (tid == 0) g_candcnt[row] = (s_cnt < CMAX) ? (int)s_cnt : CMAX;
}

// ======================================================================
// Kernel 4: refine (compensated-fp32 double-float, ~1e-11 rel) + exact
// top-32 selection. One CTA (256 thr) per row. (R14-proven.)
// ======================================================================
__global__ __launch_bounds__(256)
void refine_kernel(const float* __restrict__ X, const float* __restrict__ W,
                   const float* __restrict__ benc) {
    const int row = blockIdx.x;
    const int tid = threadIdx.x;
    const int wid = tid >> 5;
    const int lid = tid & 31;

    __shared__ float  xs[DIN];
    __shared__ double dv[CMAX];
    __shared__ int    ci[CMAX];
    __shared__ int    kept[CMAX];

    const int cnt = g_candcnt[row];
    for (int k = tid; k < DIN; k += 256) xs[k] = X[(size_t)row * DIN + k];
    for (int c = tid; c < cnt; c += 256) ci[c] = g_candi[(size_t)row * CMAX + c];
    if (tid < TK) { g_selv[row * TK + tid] = 0.f; g_seli[row * TK + tid] = 0; }
    __syncthreads();

    // double-float dot per candidate (warp-per-candidate)
    for (int c = wid; c < cnt; c += 8) {
        const int h = ci[c];
        const float* w = &W[(size_t)h * DIN];
        float hi = 0.f, lo = 0.f;
#pragma unroll 4
        for (int k = lid; k < DIN; k += 32) {
            const float a = xs[k], b = w[k];
            const float p = a * b;
            const float e = fmaf(a, b, -p);
            const float t = hi + p;
            const float bb = t - hi;
            const float err = (hi - (t - bb)) + (p - bb);
            hi = t;
            lo += e + err;
        }
#pragma unroll
        for (int off = 16; off > 0; off >>= 1) {
            const float oh = __shfl_down_sync(0xffffffffu, hi, off);
            const float ol = __shfl_down_sync(0xffffffffu, lo, off);
            const float t = hi + oh;
            const float bb = t - hi;
            const float err = (hi - (t - bb)) + (oh - bb);
            hi = t;
            lo += ol + err;
        }
        if (lid == 0) {
            const float be = benc[h];
            const float t = hi + be;
            const float bb = t - hi;
            const float err = (hi - (t - bb)) + (be - bb);
            double acc = (double)t + (double)(lo + err);
            dv[c] = acc > 0.0 ? acc : 0.0;
        }
    }
    __syncthreads();

    // exact rank (ties by lower index)
    for (int c = tid; c < cnt; c += 256) {
        const double vi = dv[c]; const int ii = ci[c];
        int rank = 0;
        for (int j = 0; j < cnt; j++) {
            const double vj = dv[j];
            rank += (vj > vi || (vj == vi && ci[j] < ii)) ? 1 : 0;
        }
        kept[c] = (rank < TK) ? 1 : 0;
    }
    __syncthreads();

    // compact kept in ascending hidden-index order
    for (int c = tid; c < cnt; c += 256) {
        if (kept[c]) {
            const int ii = ci[c];
            int slot = 0;
            for (int j = 0; j < cnt; j++)
                if (kept[j] && ci[j] < ii) slot++;
            if (slot < TK) {
                g_selv[row * TK + slot] = (float)dv[c];
                g_seli[row * TK + slot] = ii;
            }
        }
    }
}

// ======================================================================
// Kernel 5: sparse decode  out[b,:] = b_dec + sum_k v_k * WdT16[idx_k, :]
// ======================================================================
__global__ __launch_bounds__(256)
void decode_kernel(const float* __restrict__ bdec, float* __restrict__ out) {
    const int row = blockIdx.x;
    const int tid = threadIdx.x;
    __shared__ float sv[TK];
    __shared__ int   si[TK];
    if (tid < TK) {
        sv[tid] = g_selv[row * TK + tid];
        si[tid] = g_seli[row * TK + tid];
    }
    __syncthreads();

    float acc0 = bdec[tid];
    float acc1 = bdec[tid + 256];
    float acc2 = bdec[tid + 512];
#pragma unroll 8
    for (int k = 0; k < TK; k++) {
        const float vv = sv[k];
        const __half* w = &g_wdth[(size_t)si[k] * DIN];
        acc0 = fmaf(vv, __half2float(w[tid]),       acc0);
        acc1 = fmaf(vv, __half2float(w[tid + 256]), acc1);
        acc2 = fmaf(vv, __half2float(w[tid + 512]), acc2);
    }
    float* o = &out[(size_t)row * DIN];
    o[tid]       = acc0;
    o[tid + 256] = acc1;
    o[tid + 512] = acc2;
}

// ======================================================================
// launch — linear best-of-breed composition (R14 structure, uint8 z)
// ======================================================================
extern "C" void kernel_launch(void* const* d_in, const int* in_sizes, int n_in,
                              void* d_out, int out_size) {
    const float* x     = (const float*)d_in[0];   // [8192, 768]
    const float* w_enc = (const float*)d_in[1];   // [16384, 768]
    const float* b_enc = (const float*)d_in[2];   // [16384]
    const float* w_dec = (const float*)d_in[3];   // [768, 16384]
    const float* b_dec = (const float*)d_in[4];   // [768]
    float* out = (float*)d_out;                   // [8192, 768]

    static int enc_attr_set = 0;
    if (!enc_attr_set) {
        cudaFuncSetAttribute(encode_mma, cudaFuncAttributeMaxDynamicSharedMemorySize, ENC_SMEM);
        enc_attr_set = 1;
    }

    // 0. bf16 copies of X, W_enc
    __nv_bfloat16* xbf; cudaGetSymbolAddress((void**)&xbf, g_xbf);
    __nv_bfloat16* wbf; cudaGetSymbolAddress((void**)&wbf, g_wbf);
    {
        const int n4x = BATCH * DIN / 4;
        cvt_bf16_kernel<<<(n4x + 255) / 256, 256>>>(x, xbf, n4x);
        const int n4w = DH * DIN / 4;
        cvt_bf16_kernel<<<(n4w + 255) / 256, 256>>>(w_enc, wbf, n4w);
    }
    // 1. transpose W_dec -> fp16
    {
        dim3 grid(DH / 32, DIN / 32);
        dim3 block(32, 8);
        transpose_wdec<<<grid, block>>>(w_dec);
    }
    // 2. HMMA bf16 encode GEMM + bias + relu -> uint8 z (R7 config)
    {
        dim3 grid(DH / 128, BATCH / 128);
        encode_mma<<<grid, 256, ENC_SMEM>>>(xbf, wbf, b_enc);
    }
    // 3. per-row candidate capture (256-bin byte histogram)
    hist_kernel<<<BATCH, 256>>>();
    // 4. exact top-32 via compensated-precision refinement
    refine_kernel<<<BATCH, 256>>>(x, w_enc, b_enc);
    // 5. sparse decode (fp16 W_dec^T)
    decode_kernel<<<BATCH, 256>>>(b_dec, out);
}

// round 16
// speedup vs baseline: 1.7714x; 1.0048x over previous
#include <cuda_runtime.h>
#include <cuda_bf16.h>
#include <cuda_fp16.h>
#include <cstdint>
#include <climits>

#define BATCH 8192
#define DIN   768
#define DH    16384
#define TK    32
#define CMAX  512
#define CUMTGT 44
#define QMIN  64            // only histogram q >= 64 (z >= 0.75)
#define QSCALE (256.0f / 3.0f)

// ---- scratch (static device globals; no dynamic allocation) ----
__device__ uint8_t g_zq[(size_t)BATCH * DH];         // 128 MB quantized z
__device__ __half g_wdth[(size_t)DH * DIN];          // 24 MB transposed W_dec (fp16)
__device__ __nv_bfloat16 g_xbf[(size_t)BATCH * DIN];
__device__ __nv_bfloat16 g_wbf[(size_t)DH * DIN];
__device__ int   g_candi[(size_t)BATCH * CMAX];
__device__ int   g_candcnt[BATCH];
__device__ float g_selv[BATCH * TK];
__device__ int   g_seli[BATCH * TK];

// ======================================================================
// helpers (all target-independent PTX: cp.async, ldmatrix, mma.sync)
// ======================================================================
__device__ __forceinline__ uint32_t smem_u32(const void* p) {
    uint32_t a;
    asm("{ .reg .u64 t; cvta.to.shared.u64 t, %1; cvt.u32.u64 %0, t; }" : "=r"(a) : "l"(p));
    return a;
}
__device__ __forceinline__ void cpa16(uint32_t dst, const void* src) {
    asm volatile("cp.async.cg.shared.global [%0], [%1], 16;" :: "r"(dst), "l"(src));
}
#define CP_COMMIT() asm volatile("cp.async.commit_group;" ::: "memory")
#define CP_WAIT(n)  asm volatile("cp.async.wait_group %0;" :: "n"(n) : "memory")

__device__ __forceinline__ void ldm_x4(uint32_t* r, uint32_t addr) {
    asm volatile("ldmatrix.sync.aligned.m8n8.x4.shared.b16 {%0,%1,%2,%3}, [%4];"
        : "=r"(r[0]), "=r"(r[1]), "=r"(r[2]), "=r"(r[3]) : "r"(addr));
}
__device__ __forceinline__ void mma16816(float* d, const uint32_t* a, uint32_t b0, uint32_t b1) {
    asm volatile(
        "mma.sync.aligned.m16n8k16.row.col.f32.bf16.bf16.f32 "
        "{%0,%1,%2,%3}, {%4,%5,%6,%7}, {%8,%9}, {%0,%1,%2,%3};"
        : "+f"(d[0]), "+f"(d[1]), "+f"(d[2]), "+f"(d[3])
        : "r"(a[0]), "r"(a[1]), "r"(a[2]), "r"(a[3]), "r"(b0), "r"(b1));
}
__device__ __forceinline__ uint32_t quant_z(float z) {
    const float s = fminf(fmaxf(z * QSCALE, 0.f), 255.f);
    return (uint32_t)s;   // truncation: monotone
}

// ======================================================================
// Kernel 0: fp32 -> bf16 conversion (vectorized)
// ======================================================================
__global__ void cvt_bf16_kernel(const float* __restrict__ s, __nv_bfloat16* __restrict__ d, int n4) {
    const int i = blockIdx.x * 256 + threadIdx.x;
    if (i < n4) {
        const float4 v = ((const float4*)s)[i];
        ((__nv_bfloat162*)d)[i * 2 + 0] = __floats2bfloat162_rn(v.x, v.y);
        ((__nv_bfloat162*)d)[i * 2 + 1] = __floats2bfloat162_rn(v.z, v.w);
    }
}

// ======================================================================
// Kernel 1: transpose W_dec [DIN, DH] -> g_wdth [DH, DIN]  (fp16)
// ======================================================================
__global__ void transpose_wdec(const float* __restrict__ wdec) {
    __shared__ float tile[32][33];
    const int h0 = blockIdx.x * 32;
    const int i0 = blockIdx.y * 32;
#pragma unroll
    for (int j = 0; j < 32; j += 8)
        tile[threadIdx.y + j][threadIdx.x] =
            wdec[(size_t)(i0 + threadIdx.y + j) * DH + (h0 + threadIdx.x)];
    __syncthreads();
#pragma unroll
    for (int j = 0; j < 32; j += 8)
        g_wdth[(size_t)(h0 + threadIdx.y + j) * DIN + (i0 + threadIdx.x)] =
            __float2half(tile[threadIdx.x][threadIdx.y + j]);
}

// ======================================================================
// Kernel 2: HMMA bf16 encode GEMM  z = relu(X @ W^T + b) -> uint8 quant
//   R7 mainloop (best measured, 6x reproduced): BM=BN=128, BK=32,
//   3-stage cp.async, PITCH=80 conflict-free ldmatrix, 8 warps 4(m)x2(n),
//   32x64 warp tile, 2 CTAs/SM. Epilogue: quantize -> smem stage ->
//   128B-coalesced uint4 global stores (fixes R15's 2B-store replays).
// ======================================================================
#define EBK 32
#define PITCH 80
#define NKB (DIN / EBK)                  // 24
#define STG_BYTES (128 * PITCH)          // 10240 per tile
#define STAGE_BYTES (2 * STG_BYTES)      // A + B = 20480
#define ENC_SMEM (3 * STAGE_BYTES + 512) // 61952

__device__ __forceinline__ void enc_load(char* sA, char* sB,
                                         const __nv_bfloat16* __restrict__ X,
                                         const __nv_bfloat16* __restrict__ W,
                                         int bm, int bn, int kc, int tid) {
    const int k0 = kc * EBK;
#pragma unroll
    for (int i = 0; i < 2; i++) {
        const int cid = tid + i * 256;          // 512 chunks: 128 rows x 4 x 16B
        const int r = cid >> 2, c = cid & 3;
        cpa16(smem_u32(sA + r * PITCH + c * 16), &X[(size_t)(bm + r) * DIN + k0 + c * 8]);
        cpa16(smem_u32(sB + r * PITCH + c * 16), &W[(size_t)(bn + r) * DIN + k0 + c * 8]);
    }
    CP_COMMIT();
}

__global__ __launch_bounds__(256, 2)
void encode_mma(const __nv_bfloat16* __restrict__ X, const __nv_bfloat16* __restrict__ W,
                const float* __restrict__ benc) {
    extern __shared__ __align__(16) char smem[];
    float* sbias = (float*)(smem + 3 * STAGE_BYTES);

    const int tid = threadIdx.x;
    const int lane = tid & 31;
    const int wid = tid >> 5;
    const int warp_m = wid & 3;
    const int warp_n = wid >> 2;
    const int bm = blockIdx.y * 128;
    const int bn = blockIdx.x * 128;

    if (tid < 128) sbias[tid] = benc[bn + tid];

    float d[2][8][4];
#pragma unroll
    for (int mt = 0; mt < 2; mt++)
#pragma unroll
        for (int nt = 0; nt < 8; nt++)
#pragma unroll
            for (int q = 0; q < 4; q++) d[mt][nt][q] = 0.f;

    const int a_row = warp_m * 32 + (lane & 15);
    const int a_kb  = ((lane >> 4) & 1) * 16;
    const int b_row = warp_n * 64 + (lane & 7) + ((lane >> 4) << 3);
    const int b_kb  = ((lane >> 3) & 1) * 16;

    enc_load(smem + 0 * STAGE_BYTES, smem + 0 * STAGE_BYTES + STG_BYTES, X, W, bm, bn, 0, tid);
    enc_load(smem + 1 * STAGE_BYTES, smem + 1 * STAGE_BYTES + STG_BYTES, X, W, bm, bn, 1, tid);

    int cur = 0, nxt2 = 2;
    for (int kb = 0; kb < NKB; kb++) {
        if (kb >= NKB - 1) { CP_WAIT(0); } else { CP_WAIT(1); }
        __syncthreads();   // stage cur ready; stage nxt2 free for reuse

        if (kb + 2 < NKB) {
            char* base = smem + nxt2 * STAGE_BYTES;
            enc_load(base, base + STG_BYTES, X, W, bm, bn, kb + 2, tid);
        }

        char* cA = smem + cur * STAGE_BYTES;
        char* cB = cA + STG_BYTES;
#pragma unroll
        for (int s = 0; s < 2; s++) {          // two k16 steps per 32-chunk
            uint32_t a[2][4], b[4][4];
#pragma unroll
            for (int mt = 0; mt < 2; mt++)
                ldm_x4(a[mt], smem_u32(cA + (a_row + mt * 16) * PITCH + s * 32 + a_kb));
#pragma unroll
            for (int p = 0; p < 4; p++)
                ldm_x4(b[p], smem_u32(cB + (b_row + p * 16) * PITCH + s * 32 + b_kb));
#pragma unroll
            for (int mt = 0; mt < 2; mt++)
#pragma unroll
                for (int p = 0; p < 4; p++) {
                    mma16816(d[mt][2 * p],     a[mt], b[p][0], b[p][1]);
                    mma16816(d[mt][2 * p + 1], a[mt], b[p][2], b[p][3]);
                }
        }
        cur = (cur + 1) % 3;
        nxt2 = (nxt2 + 1) % 3;
    }

    // epilogue: bias + relu + uint8 quant -> smem stage -> coalesced stores
    __syncthreads();                     // mainloop smem now dead
    uint8_t* qt = (uint8_t*)smem;        // staging tile [128 rows][128 cols]
#pragma unroll
    for (int mt = 0; mt < 2; mt++) {
        const int rl = warp_m * 32 + mt * 16 + (lane >> 2);
#pragma unroll
        for (int nt = 0; nt < 8; nt++) {
            const int cl = warp_n * 64 + nt * 8 + (lane & 3) * 2;
            const float b0 = sbias[cl], b1 = sbias[cl + 1];
            const uint32_t q00 = quant_z(d[mt][nt][0] + b0);
            const uint32_t q01 = quant_z(d[mt][nt][1] + b1);
            const uint32_t q10 = quant_z(d[mt][nt][2] + b0);
            const uint32_t q11 = quant_z(d[mt][nt][3] + b1);
            *(uint16_t*)&qt[rl * 128 + cl]       = (uint16_t)(q00 | (q01 << 8));
            *(uint16_t*)&qt[(rl + 8) * 128 + cl] = (uint16_t)(q10 | (q11 << 8));
        }
    }
    __syncthreads();
    // 16 KB tile out: 1024 uint4, 4 per thread, 128B rows fully coalesced
#pragma unroll
    for (int k = 0; k < 4; k++) {
        const int idx = tid + k * 256;
        const int r = idx >> 3;
        const int c = (idx & 7) * 16;
        *(uint4*)&g_zq[(size_t)(bm + r) * DH + bn + c] = *(const uint4*)&qt[r * 128 + c];
    }
}

// ======================================================================
// Kernel 3: 256-bin byte histogram candidate select. One CTA per row.
// Row = 16384 bytes = 1024 uint4; each thread owns 4 coalesced uint4.
// Only q >= QMIN counted. Capture = all q >= cut: superset of the true
// top-CUMTGT by monotonicity of the quantizer.
// ======================================================================
__global__ __launch_bounds__(256)
void hist_kernel() {
    const int row = blockIdx.x;
    const int tid = threadIdx.x;
    __shared__ uint32_t hist[256];
    __shared__ uint32_t s_cut;
    __shared__ uint32_t s_cnt;

    hist[tid] = 0;
    if (tid == 0) s_cnt = 0;
    __syncthreads();

    const uint4* z4 = (const uint4*)&g_zq[(size_t)row * DH];
    uint32_t v[16];
#pragma unroll
    for (int j = 0; j < 4; j++) {
        const uint4 t = z4[tid + j * 256];
        v[j * 4 + 0] = t.x; v[j * 4 + 1] = t.y; v[j * 4 + 2] = t.z; v[j * 4 + 3] = t.w;
    }
#pragma unroll
    for (int j = 0; j < 16; j++) {
#pragma unroll
        for (int b = 0; b < 4; b++) {
            const uint32_t q = (v[j] >> (8 * b)) & 255u;
            if (q >= QMIN) atomicAdd(&hist[q], 1u);
        }
    }
    __syncthreads();

    if (tid == 0) {
        uint32_t cum = 0; int b = 255;
        for (; b >= QMIN; --b) {
            cum += hist[b];
            if (cum >= CUMTGT) break;
        }
        s_cut = (b < QMIN) ? QMIN : (uint32_t)b;
    }
    __syncthreads();

    const uint32_t cut = s_cut;
#pragma unroll
    for (int j = 0; j < 16; j++) {
        const int u = tid + (j >> 2) * 256;       // uint4 index within row
        const int base = u * 16 + (j & 3) * 4;    // byte (element) index
#pragma unroll
        for (int b = 0; b < 4; b++) {
            const uint32_t q = (v[j] >> (8 * b)) & 255u;
            if (q >= cut) {
                const int p = atomicAdd(&s_cnt, 1u);
                if (p < CMAX) g_candi[(size_t)row * CMAX + p] = base + b;
            }
        }
    }
    __syncthreads();
    if (tid == 0) g_candcnt[row] = (s_cnt < CMAX) ? (int)s_cnt : CMAX;
}

// ======================================================================
// Kernel 4: refine (compensated-fp32 double-float, ~1e-11 rel) + exact
// top-32 selection. One CTA (256 thr) per row. (R14/R15-proven.)
// ======================================================================
__global__ __launch_bounds__(256)
void refine_kernel(const float* __restrict__ X, const float* __restrict__ W,
                   const float* __restrict__ benc) {
    const int row = blockIdx.x;
    const int tid = threadIdx.x;
    const int wid = tid >> 5;
    const int lid = tid & 31;

    __shared__ float  xs[DIN];
    __shared__ double dv[CMAX];
    __shared__ int    ci[CMAX];
    __shared__ int    kept[CMAX];

    const int cnt = g_candcnt[row];
    for (int k = tid; k < DIN; k += 256) xs[k] = X[(size_t)row * DIN + k];
    for (int c = tid; c < cnt; c += 256) ci[c] = g_candi[(size_t)row * CMAX + c];
    if (tid < TK) { g_selv[row * TK + tid] = 0.f; g_seli[row * TK + tid] = 0; }
    __syncthreads();

    // double-float dot per candidate (warp-per-candidate)
    for (int c = wid; c < cnt; c += 8) {
        const int h = ci[c];
        const float* w = &W[(size_t)h * DIN];
        float hi = 0.f, lo = 0.f;
#pragma unroll 4
        for (int k = lid; k < DIN; k += 32) {
            const float a = xs[k], b = w[k];
            const float p = a * b;
            const float e = fmaf(a, b, -p);
            const float t = hi + p;
            const float bb = t - hi;
            const float err = (hi - (t - bb)) + (p - bb);
            hi = t;
            lo += e + err;
        }
#pragma unroll
        for (int off = 16; off > 0; off >>= 1) {
            const float oh = __shfl_down_sync(0xffffffffu, hi, off);
            const float ol = __shfl_down_sync(0xffffffffu, lo, off);
            const float t = hi + oh;
            const float bb = t - hi;
            const float err = (hi - (t - bb)) + (oh - bb);
            hi = t;
            lo += ol + err;
        }
        if (lid == 0) {
            const float be = benc[h];
            const float t = hi + be;
            const float bb = t - hi;
            const float err = (hi - (t - bb)) + (be - bb);
            double acc = (double)t + (double)(lo + err);
            dv[c] = acc > 0.0 ? acc : 0.0;
        }
    }
    __syncthreads();

    // exact rank (ties by lower index)
    for (int c = tid; c < cnt; c += 256) {
        const double vi = dv[c]; const int ii = ci[c];
        int rank = 0;
        for (int j = 0; j < cnt; j++) {
            const double vj = dv[j];
            rank += (vj > vi || (vj == vi && ci[j] < ii)) ? 1 : 0;
        }
        kept[c] = (rank < TK) ? 1 : 0;
    }
    __syncthreads();

    // compact kept in ascending hidden-index order
    for (int c = tid; c < cnt; c += 256) {
        if (kept[c]) {
            const int ii = ci[c];
            int slot = 0;
            for (int j = 0; j < cnt; j++)
                if (kept[j] && ci[j] < ii) slot++;
            if (slot < TK) {
                g_selv[row * TK + slot] = (float)dv[c];
                g_seli[row * TK + slot] = ii;
            }
        }
    }
}

// ======================================================================
// Kernel 5: sparse decode  out[b,:] = b_dec + sum_k v_k * WdT16[idx_k, :]
// ======================================================================
__global__ __launch_bounds__(256)
void decode_kernel(const float* __restrict__ bdec, float* __restrict__ out) {
    const int row = blockIdx.x;
    const int tid = threadIdx.x;
    __shared__ float sv[TK];
    __shared__ int   si[TK];
    if (tid < TK) {
        sv[tid] = g_selv[row * TK + tid];
        si[tid] = g_seli[row * TK + tid];
    }
    __syncthreads();

    float acc0 = bdec[tid];
    float acc1 = bdec[tid + 256];
    float acc2 = bdec[tid + 512];
#pragma unroll 8
    for (int k = 0; k < TK; k++) {
        const float vv = sv[k];
        const __half* w = &g_wdth[(size_t)si[k] * DIN];
        acc0 = fmaf(vv, __half2float(w[tid]),       acc0);
        acc1 = fmaf(vv, __half2float(w[tid + 256]), acc1);
        acc2 = fmaf(vv, __half2float(w[tid + 512]), acc2);
    }
    float* o = &out[(size_t)row * DIN];
    o[tid]       = acc0;
    o[tid + 256] = acc1;
    o[tid + 512] = acc2;
}

// ======================================================================
// launch — linear best-of-breed composition (R15 structure, staged stores)
// ======================================================================
extern "C" void kernel_launch(void* const* d_in, const int* in_sizes, int n_in,
                              void* d_out, int out_size) {
    const float* x     = (const float*)d_in[0];   // [8192, 768]
    const float* w_enc = (const float*)d_in[1];   // [16384, 768]
    const float* b_enc = (const float*)d_in[2];   // [16384]
    const float* w_dec = (const float*)d_in[3];   // [768, 16384]
    const float* b_dec = (const float*)d_in[4];   // [768]
    float* out = (float*)d_out;                   // [8192, 768]

    static int enc_attr_set = 0;
    if (!enc_attr_set) {
        cudaFuncSetAttribute(encode_mma, cudaFuncAttributeMaxDynamicSharedMemorySize, ENC_SMEM);
        enc_attr_set = 1;
    }

    // 0. bf16 copies of X, W_enc
    __nv_bfloat16* xbf; cudaGetSymbolAddress((void**)&xbf, g_xbf);
    __nv_bfloat16* wbf; cudaGetSymbolAddress((void**)&wbf, g_wbf);
    {
        const int n4x = BATCH * DIN / 4;
        cvt_bf16_kernel<<<(n4x + 255) / 256, 256>>>(x, xbf, n4x);
        const int n4w = DH * DIN / 4;
        cvt_bf16_kernel<<<(n4w + 255) / 256, 256>>>(w_enc, wbf, n4w);
    }
    // 1. transpose W_dec -> fp16
    {
        dim3 grid(DH / 32, DIN / 32);
        dim3 block(32, 8);
        transpose_wdec<<<grid, block>>>(w_dec);
    }
    // 2. HMMA bf16 encode GEMM + bias + relu -> uint8 z (staged stores)
    {
        dim3 grid(DH / 128, BATCH / 128);
        encode_mma<<<grid, 256, ENC_SMEM>>>(xbf, wbf, b_enc);
    }
    // 3. per-row candidate capture (256-bin byte histogram)
    hist_kernel<<<BATCH, 256>>>();
    // 4. exact top-32 via compensated-precision refinement
    refine_kernel<<<BATCH, 256>>>(x, w_enc, b_enc);
    // 5. sparse decode (fp16 W_dec^T)
    decode_kernel<<<BATCH, 256>>>(b_dec, out);
}